// round 2
// baseline (speedup 1.0000x reference)
#include <cuda_runtime.h>
#include <cstdint>

// Problem constants (fixed by the dataset)
#define NN 50000
#define EE 800000
#define FF 64
#define HH 128
#define CAP 96   // ELL capacity per row; deg ~ Poisson(16), P(deg>96) ~ 0

typedef unsigned long long ull;

// ---------------- scratch (static device globals; no allocations) -----------
__device__ int   g_cnt[NN];
__device__ float g_dinv[NN];
__device__ int   g_ell[(size_t)NN * CAP];          // neighbor col only (4B)
__device__ float g_XS [(size_t)NN * FF];           // dinv * X
__device__ float g_T1 [(size_t)NN * FF];
__device__ float g_T1S[(size_t)NN * FF];           // dinv * T1
__device__ float g_T2 [(size_t)NN * FF];
__device__ float g_T2S[(size_t)NN * FF];           // dinv * T2
__device__ float g_T3 [(size_t)NN * FF];

// ---------------- packed f32x2 helpers ---------------------------------------
__device__ __forceinline__ void fma2(ull& d, ull a, ull b) {
    asm("fma.rn.f32x2 %0, %1, %2, %0;" : "+l"(d) : "l"(a), "l"(b));
}
__device__ __forceinline__ void upk2(ull v, float& lo, float& hi) {
    asm("mov.b64 {%0, %1}, %2;" : "=f"(lo), "=f"(hi) : "l"(v));
}

// ---------------- graph build ------------------------------------------------
__global__ void k_zero_cnt() {
    int i = blockIdx.x * blockDim.x + threadIdx.x;
    if (i < NN) g_cnt[i] = 0;
}

__global__ void k_fill(const int* __restrict__ ei) {
    int e = blockIdx.x * blockDim.x + threadIdx.x;
    if (e >= EE) return;
    int r = ei[e];
    int c = ei[EE + e];
    int s = atomicAdd(&g_cnt[r], 1);
    if (s < CAP) g_ell[(size_t)r * CAP + s] = c;
}

__global__ void k_dinv() {
    int i = blockIdx.x * blockDim.x + threadIdx.x;
    if (i >= NN) return;
    int d = g_cnt[i];
    g_dinv[i] = (d > 0) ? rsqrtf((float)d) : 0.0f;
}

// XS = dinv[row] * X  (one float4 per thread)
__global__ void k_scale(const float* __restrict__ x) {
    int idx = blockIdx.x * blockDim.x + threadIdx.x;
    if (idx >= NN * (FF / 4)) return;
    int row = idx >> 4;
    float d = g_dinv[row];
    float4 v = ((const float4*)x)[idx];
    v.x *= d; v.y *= d; v.z *= d; v.w *= d;
    ((float4*)g_XS)[idx] = v;
}

// ---------------- SPMM: warp per row, weight-free gather of pre-scaled src ---
// spmm(z)[r] = -dinv[r] * sum_{c in N(r)} (dinv*z)[c]
// PHASE 1: T1 =   L*X        = -dinv[r]*S(XS)            ; also T1S
// PHASE 2: T2 = 2*L*T1 - X   = -2*dinv[r]*S(T1S) - X[r]  ; also T2S
// PHASE 3: T3 = 2*L*T2 - T1  = -2*dinv[r]*S(T2S) - T1[r]
template <int PHASE>
__global__ void k_spmm(const float* __restrict__ x) {
    int row  = (blockIdx.x * blockDim.x + threadIdx.x) >> 5;
    int lane = threadIdx.x & 31;
    if (row >= NN) return;
    int l2 = lane * 2;

    const float* __restrict__ srcS = (PHASE == 1) ? g_XS
                                   : (PHASE == 2) ? g_T1S : g_T2S;
    const float* __restrict__ prev = (PHASE == 2) ? x
                                   : (PHASE == 3) ? g_T1 : nullptr;
    float* __restrict__ dst  = (PHASE == 1) ? g_T1
                             : (PHASE == 2) ? g_T2 : g_T3;
    float* __restrict__ dstS = (PHASE == 1) ? g_T1S
                             : (PHASE == 2) ? g_T2S : nullptr;

    int cnt = g_cnt[row]; if (cnt > CAP) cnt = CAP;
    const int* ep = g_ell + (size_t)row * CAP;

    float ax = 0.f, ay = 0.f;
    int i = 0;
    int n8 = cnt & ~7;
    for (; i < n8; i += 8) {                       // 8 gathers in flight
        int4 ca = *(const int4*)(ep + i);
        int4 cb = *(const int4*)(ep + i + 4);
        float2 v0 = *(const float2*)(srcS + (size_t)ca.x * FF + l2);
        float2 v1 = *(const float2*)(srcS + (size_t)ca.y * FF + l2);
        float2 v2 = *(const float2*)(srcS + (size_t)ca.z * FF + l2);
        float2 v3 = *(const float2*)(srcS + (size_t)ca.w * FF + l2);
        float2 v4 = *(const float2*)(srcS + (size_t)cb.x * FF + l2);
        float2 v5 = *(const float2*)(srcS + (size_t)cb.y * FF + l2);
        float2 v6 = *(const float2*)(srcS + (size_t)cb.z * FF + l2);
        float2 v7 = *(const float2*)(srcS + (size_t)cb.w * FF + l2);
        ax += v0.x + v1.x + v2.x + v3.x + v4.x + v5.x + v6.x + v7.x;
        ay += v0.y + v1.y + v2.y + v3.y + v4.y + v5.y + v6.y + v7.y;
    }
    int n4 = cnt & ~3;
    for (; i < n4; i += 4) {
        int4 ca = *(const int4*)(ep + i);
        float2 v0 = *(const float2*)(srcS + (size_t)ca.x * FF + l2);
        float2 v1 = *(const float2*)(srcS + (size_t)ca.y * FF + l2);
        float2 v2 = *(const float2*)(srcS + (size_t)ca.z * FF + l2);
        float2 v3 = *(const float2*)(srcS + (size_t)ca.w * FF + l2);
        ax += v0.x + v1.x + v2.x + v3.x;
        ay += v0.y + v1.y + v2.y + v3.y;
    }
    for (; i < cnt; i++) {
        float2 v = *(const float2*)(srcS + (size_t)ep[i] * FF + l2);
        ax += v.x; ay += v.y;
    }

    float d = g_dinv[row];
    float2 res;
    if (PHASE == 1) {
        res.x = -d * ax;
        res.y = -d * ay;
    } else {
        float2 p = *(const float2*)(prev + (size_t)row * FF + l2);
        float m = -2.f * d;
        res.x = fmaf(m, ax, -p.x);
        res.y = fmaf(m, ay, -p.y);
    }
    *(float2*)(dst + (size_t)row * FF + l2) = res;
    if (PHASE <= 2) {
        float2 rs; rs.x = d * res.x; rs.y = d * res.y;
        *(float2*)(dstS + (size_t)row * FF + l2) = rs;
    }
}

// ---------------- fused GEMM + bias + tanh + final dot -----------------------
// out[n,h] = sum_k T_k[n,:]@W_k[:,h] + b[h];  y[n] = sum_h tanh(out)*fw[h] + fb
// Tile: 128 rows x 128 cols (all of H), K=256 in 8 chunks of 32.
// A staged in smem PRE-DUPLICATED as float2{a,a} -> LDS.64 yields packed
// multiplicand directly; B pairs (h,h+1) contiguous -> LDS.128 reinterpreted
// as 2 packed u64. Inner loop: 8 LDS.64 + 2 LDS.128 + 32 FFMA2, zero movs.
__global__ __launch_bounds__(256, 2)
void k_gemm(const float* __restrict__ X, const float* __restrict__ W,
            const float* __restrict__ bias, const float* __restrict__ fw,
            const float* __restrict__ fb, float* __restrict__ y) {
    __shared__ float2 As[128][32];   // [row][kk] duplicated {a,a}  (32 KB)
    __shared__ float  Bs[32][128];   // [kk][h]                     (16 KB)

    int tid = threadIdx.x;
    int tx = tid & 15, ty = tid >> 4;
    int rowBase = blockIdx.x * 128;

    ull acc[8][4];
#pragma unroll
    for (int i = 0; i < 8; i++)
#pragma unroll
        for (int j = 0; j < 4; j++) acc[i][j] = 0ull;

    const float* srcs[4] = {X, g_T1, g_T2, g_T3};

    for (int ch = 0; ch < 8; ch++) {
        const float* A  = srcs[ch >> 1];
        int kofs        = (ch & 1) * 32;
        const float* Bp = W + (ch >> 1) * (FF * HH) + kofs * HH;

#pragma unroll
        for (int t = 0; t < 4; t++) {
            int g = t * 256 + tid;          // 0..1023 float4s
            int r = g >> 3, c4 = g & 7;     // 8 float4 per 32-wide A row
            int grow = rowBase + r;
            float4 v = make_float4(0.f, 0.f, 0.f, 0.f);
            if (grow < NN)
                v = *(const float4*)(A + (size_t)grow * FF + kofs + c4 * 4);
            // duplicated stores: {v.x,v.x,v.y,v.y} {v.z,v.z,v.w,v.w}
            *(float4*)&As[r][c4 * 4]     = make_float4(v.x, v.x, v.y, v.y);
            *(float4*)&As[r][c4 * 4 + 2] = make_float4(v.z, v.z, v.w, v.w);
            ((float4*)Bs)[g] = ((const float4*)Bp)[g];
        }
        __syncthreads();

#pragma unroll 8
        for (int kk = 0; kk < 32; kk++) {
            const ull* bp = (const ull*)&Bs[kk][tx * 8];
            ull w0 = bp[0], w1 = bp[1], w2 = bp[2], w3 = bp[3];
#pragma unroll
            for (int i = 0; i < 8; i++) {
                ull a2 = *(const ull*)&As[ty * 8 + i][kk];
                fma2(acc[i][0], a2, w0);
                fma2(acc[i][1], a2, w1);
                fma2(acc[i][2], a2, w2);
                fma2(acc[i][3], a2, w3);
            }
        }
        __syncthreads();
    }

    // epilogue: bias + tanh + dot with fw, reduce over the 16 tx lanes
    float bia[8], fwv[8];
#pragma unroll
    for (int j = 0; j < 8; j++) {
        bia[j] = bias[tx * 8 + j];
        fwv[j] = fw[tx * 8 + j];
    }
    float fbv = fb[0];

    float part[8];
#pragma unroll
    for (int i = 0; i < 8; i++) {
        float p = 0.f;
#pragma unroll
        for (int jj = 0; jj < 4; jj++) {
            float lo, hi;
            upk2(acc[i][jj], lo, hi);
            p += tanhf(lo + bia[jj * 2])     * fwv[jj * 2];
            p += tanhf(hi + bia[jj * 2 + 1]) * fwv[jj * 2 + 1];
        }
        part[i] = p;
    }
#pragma unroll
    for (int ofs = 8; ofs > 0; ofs >>= 1)
#pragma unroll
        for (int i = 0; i < 8; i++)
            part[i] += __shfl_xor_sync(0xffffffffu, part[i], ofs);

    if (tx == 0) {
#pragma unroll
        for (int i = 0; i < 8; i++) {
            int r = rowBase + ty * 8 + i;
            if (r < NN) y[r] = part[i] + fbv;
        }
    }
}

// ---------------- launch -----------------------------------------------------
extern "C" void kernel_launch(void* const* d_in, const int* in_sizes, int n_in,
                              void* d_out, int out_size) {
    const float* features = (const float*)d_in[0];
    const int*   ei       = (const int*)d_in[1];
    const float* cheb_w   = (const float*)d_in[2];
    const float* cheb_b   = (const float*)d_in[3];
    const float* final_w  = (const float*)d_in[4];
    const float* final_b  = (const float*)d_in[5];
    float* y = (float*)d_out;

    k_zero_cnt<<<(NN + 255) / 256, 256>>>();
    k_fill<<<(EE + 255) / 256, 256>>>(ei);
    k_dinv<<<(NN + 255) / 256, 256>>>();
    k_scale<<<(NN * (FF / 4) + 255) / 256, 256>>>(features);

    int spmm_blocks = (NN + 7) / 8;          // 8 warp-rows per 256-thread block
    k_spmm<1><<<spmm_blocks, 256>>>(features);
    k_spmm<2><<<spmm_blocks, 256>>>(features);
    k_spmm<3><<<spmm_blocks, 256>>>(features);

    int gemm_blocks = (NN + 127) / 128;
    k_gemm<<<gemm_blocks, 256>>>(features, cheb_w, cheb_b, final_w, final_b, y);
}

// round 4
// speedup vs baseline: 1.2939x; 1.2939x over previous
#include <cuda_runtime.h>
#include <cuda_bf16.h>
#include <cstdint>

// Problem constants (fixed by the dataset)
#define NN 50000
#define EE 800000
#define FF 64
#define HH 128
#define CAP 96   // ELL capacity per row; deg ~ Poisson(16), P(deg>96) ~ 0

typedef unsigned long long ull;
typedef __nv_bfloat16 bf16;

// ---------------- scratch (static device globals; no allocations) -----------
__device__ int   g_cnt[NN];
__device__ float g_dinv[NN];
__device__ int   g_ell[(size_t)NN * CAP];   // neighbor col only (4B)
__device__ float g_XS [(size_t)NN * FF];    // dinv * X
__device__ float g_T1 [(size_t)NN * FF];    // f32 T1 (prev for phase 3)
__device__ float g_T1S[(size_t)NN * FF];
__device__ float g_T2S[(size_t)NN * FF];
// bf16 hi/lo planes consumed by the HMMA GEMM
__device__ bf16 g_Xhi [(size_t)NN * FF];
__device__ bf16 g_Xlo [(size_t)NN * FF];
__device__ bf16 g_T1hi[(size_t)NN * FF];
__device__ bf16 g_T1lo[(size_t)NN * FF];
__device__ bf16 g_T2hi[(size_t)NN * FF];
__device__ bf16 g_T2lo[(size_t)NN * FF];
__device__ bf16 g_T3hi[(size_t)NN * FF];
__device__ bf16 g_T3lo[(size_t)NN * FF];
__device__ bf16 g_Bhi[128 * 256];           // B^T hi  [h][kidx]
__device__ bf16 g_Blo[128 * 256];           // B^T lo

// ---------------- helpers ----------------------------------------------------
__device__ __forceinline__ float tanh_ap(float x) {
    float r;
    asm("tanh.approx.f32 %0, %1;" : "=f"(r) : "f"(x));
    return r;
}

__device__ __forceinline__ void mma16816(float& d0, float& d1, float& d2, float& d3,
                                         uint32_t a0, uint32_t a1, uint32_t a2, uint32_t a3,
                                         uint32_t b0, uint32_t b1) {
    asm volatile(
        "mma.sync.aligned.m16n8k16.row.col.f32.bf16.bf16.f32 "
        "{%0,%1,%2,%3}, {%4,%5,%6,%7}, {%8,%9}, {%0,%1,%2,%3};"
        : "+f"(d0), "+f"(d1), "+f"(d2), "+f"(d3)
        : "r"(a0), "r"(a1), "r"(a2), "r"(a3), "r"(b0), "r"(b1));
}

// split f32 pair -> packed bf16x2 hi and lo
__device__ __forceinline__ void split_hilo(float x, float y,
                                           uint32_t& hp, uint32_t& lp) {
    bf16 h0 = __float2bfloat16(x), h1 = __float2bfloat16(y);
    bf16 l0 = __float2bfloat16(x - __bfloat162float(h0));
    bf16 l1 = __float2bfloat16(y - __bfloat162float(h1));
    hp = (uint32_t)__bfloat16_as_ushort(h0) | ((uint32_t)__bfloat16_as_ushort(h1) << 16);
    lp = (uint32_t)__bfloat16_as_ushort(l0) | ((uint32_t)__bfloat16_as_ushort(l1) << 16);
}

// ---------------- graph build ------------------------------------------------
__global__ void k_zero_cnt() {
    int i = blockIdx.x * blockDim.x + threadIdx.x;
    if (i < NN) g_cnt[i] = 0;
}

__global__ void k_fill(const int* __restrict__ ei) {
    int e = blockIdx.x * blockDim.x + threadIdx.x;
    if (e >= EE) return;
    int r = ei[e];
    int c = ei[EE + e];
    int s = atomicAdd(&g_cnt[r], 1);
    if (s < CAP) g_ell[(size_t)r * CAP + s] = c;
}

// combo: blocks [0, 6250): dinv + XS = dinv*X + X hi/lo planes (warp per row)
//        blocks [6250, 6378): B^T hi/lo precompute from cheb_w
#define SCALE_BLOCKS 6250
__global__ void k_prep(const float* __restrict__ x, const float* __restrict__ W) {
    int tid = threadIdx.x;
    if (blockIdx.x < SCALE_BLOCKS) {
        int row  = blockIdx.x * 8 + (tid >> 5);
        int lane = tid & 31;
        int cnt = g_cnt[row];
        float d = (cnt > 0) ? rsqrtf((float)cnt) : 0.0f;
        if (lane == 0) g_dinv[row] = d;
        int l2 = lane * 2;
        size_t idx = (size_t)row * FF + l2;
        float2 v = *(const float2*)(x + idx);
        uint32_t hp, lp;
        split_hilo(v.x, v.y, hp, lp);
        *(uint32_t*)(g_Xhi + idx) = hp;
        *(uint32_t*)(g_Xlo + idx) = lp;
        v.x *= d; v.y *= d;
        *(float2*)(g_XS + idx) = v;
    } else {
        int idx = (blockIdx.x - SCALE_BLOCKS) * 256 + tid;  // 0..32767
        int h = idx >> 8, kidx = idx & 255;
        int k4 = kidx >> 6, f = kidx & 63;
        float w = W[k4 * (FF * HH) + f * HH + h];
        bf16 hi = __float2bfloat16(w);
        bf16 lo = __float2bfloat16(w - __bfloat162float(hi));
        g_Bhi[h * 256 + kidx] = hi;
        g_Blo[h * 256 + kidx] = lo;
    }
}

// ---------------- SPMM: warp per row, weight-free gather of pre-scaled src ---
// spmm(z)[r] = -dinv[r] * sum_{c in N(r)} (dinv*z)[c]
// PHASE 1: T1 = L*X          -> writes T1(f32), T1S, T1 hi/lo
// PHASE 2: T2 = 2*L*T1 - X   -> writes T2S, T2 hi/lo
// PHASE 3: T3 = 2*L*T2 - T1  -> writes T3 hi/lo only
template <int PHASE>
__global__ void k_spmm(const float* __restrict__ x) {
    int row  = (blockIdx.x * blockDim.x + threadIdx.x) >> 5;
    int lane = threadIdx.x & 31;
    if (row >= NN) return;
    int l2 = lane * 2;

    const float* __restrict__ srcS = (PHASE == 1) ? g_XS
                                   : (PHASE == 2) ? g_T1S : g_T2S;
    const float* __restrict__ prev = (PHASE == 2) ? x
                                   : (PHASE == 3) ? g_T1 : nullptr;
    bf16* __restrict__ dhi = (PHASE == 1) ? g_T1hi
                           : (PHASE == 2) ? g_T2hi : g_T3hi;
    bf16* __restrict__ dlo = (PHASE == 1) ? g_T1lo
                           : (PHASE == 2) ? g_T2lo : g_T3lo;

    int cnt = g_cnt[row]; if (cnt > CAP) cnt = CAP;
    const int* ep = g_ell + (size_t)row * CAP;

    float ax = 0.f, ay = 0.f;
    int i = 0;
    int n8 = cnt & ~7;
    for (; i < n8; i += 8) {
        int4 ca = *(const int4*)(ep + i);
        int4 cb = *(const int4*)(ep + i + 4);
        float2 v0 = *(const float2*)(srcS + (size_t)ca.x * FF + l2);
        float2 v1 = *(const float2*)(srcS + (size_t)ca.y * FF + l2);
        float2 v2 = *(const float2*)(srcS + (size_t)ca.z * FF + l2);
        float2 v3 = *(const float2*)(srcS + (size_t)ca.w * FF + l2);
        float2 v4 = *(const float2*)(srcS + (size_t)cb.x * FF + l2);
        float2 v5 = *(const float2*)(srcS + (size_t)cb.y * FF + l2);
        float2 v6 = *(const float2*)(srcS + (size_t)cb.z * FF + l2);
        float2 v7 = *(const float2*)(srcS + (size_t)cb.w * FF + l2);
        ax += ((v0.x + v1.x) + (v2.x + v3.x)) + ((v4.x + v5.x) + (v6.x + v7.x));
        ay += ((v0.y + v1.y) + (v2.y + v3.y)) + ((v4.y + v5.y) + (v6.y + v7.y));
    }
    int n4 = cnt & ~3;
    for (; i < n4; i += 4) {
        int4 ca = *(const int4*)(ep + i);
        float2 v0 = *(const float2*)(srcS + (size_t)ca.x * FF + l2);
        float2 v1 = *(const float2*)(srcS + (size_t)ca.y * FF + l2);
        float2 v2 = *(const float2*)(srcS + (size_t)ca.z * FF + l2);
        float2 v3 = *(const float2*)(srcS + (size_t)ca.w * FF + l2);
        ax += (v0.x + v1.x) + (v2.x + v3.x);
        ay += (v0.y + v1.y) + (v2.y + v3.y);
    }
    for (; i < cnt; i++) {
        float2 v = *(const float2*)(srcS + (size_t)ep[i] * FF + l2);
        ax += v.x; ay += v.y;
    }

    float d = g_dinv[row];
    size_t idx = (size_t)row * FF + l2;
    float2 res;
    if (PHASE == 1) {
        res.x = -d * ax;
        res.y = -d * ay;
        *(float2*)(g_T1 + idx) = res;                // needed as prev in phase 3
    } else {
        float2 p = *(const float2*)(prev + idx);
        float m = -2.f * d;
        res.x = fmaf(m, ax, -p.x);
        res.y = fmaf(m, ay, -p.y);
    }
    uint32_t hp, lp;
    split_hilo(res.x, res.y, hp, lp);
    *(uint32_t*)(dhi + idx) = hp;
    *(uint32_t*)(dlo + idx) = lp;
    if (PHASE <= 2) {
        float* dstS = (PHASE == 1) ? g_T1S : g_T2S;
        float2 rs; rs.x = d * res.x; rs.y = d * res.y;
        *(float2*)(dstS + idx) = rs;
    }
}

// ---------------- HMMA GEMM + bias + tanh + final dot ------------------------
// out[n,h] = sum_k [X|T1|T2|T3][n,:] @ W[:,h] + b[h]; y[n]=sum_h tanh(out)*fw+fb
// bf16 hi/lo split: AhiBhi + AhiBlo + AloBhi.
// CTA tile 128 rows x 128 h, K in 4 chunks of 64 (chunk == source matrix).
// Warp grid 2(m) x 4(n): warp tile 64x32 via m16n8k16 (4 m-tiles x 4 n-tiles).
#define SA 72                      // smem row stride in elements (144 B)
#define OFF_AH 0
#define OFF_AL (128 * SA * 2)      // 18432
#define OFF_BH (2 * 128 * SA * 2)
#define OFF_BL (3 * 128 * SA * 2)
#define OFF_BIAS (4 * 128 * SA * 2)        // 73728
#define OFF_FW   (OFF_BIAS + 512)
#define OFF_OUT  (OFF_FW + 512)
#define SMEM_DYN (OFF_OUT + 512)

__global__ __launch_bounds__(256)
void k_gemm(const float* __restrict__ bias, const float* __restrict__ fw,
            const float* __restrict__ fb, float* __restrict__ y) {
    extern __shared__ char smem[];
    int tid  = threadIdx.x;
    int lane = tid & 31, wid = tid >> 5;
    int wm = wid >> 2, wn = wid & 3;        // warp grid 2x4
    int g = lane >> 2, t = lane & 3;        // mma groupID / threadID-in-group
    int rowBase = blockIdx.x * 128;

    if (tid < 128) {
        *(float*)(smem + OFF_BIAS + tid * 4) = bias[tid];
        *(float*)(smem + OFF_FW   + tid * 4) = fw[tid];
        *(float*)(smem + OFF_OUT  + tid * 4) = 0.f;
    }

    float acc[4][4][4];
#pragma unroll
    for (int a = 0; a < 4; a++)
#pragma unroll
        for (int b = 0; b < 4; b++)
#pragma unroll
            for (int c = 0; c < 4; c++) acc[a][b][c] = 0.f;

    const bf16* Ahi[4] = {g_Xhi, g_T1hi, g_T2hi, g_T3hi};
    const bf16* Alo[4] = {g_Xlo, g_T1lo, g_T2lo, g_T3lo};

    for (int ch = 0; ch < 4; ch++) {
        __syncthreads();
        // stage A hi/lo: 1024 16B units per plane; unit u: row=u>>3, j=u&7
        const bf16* ah = Ahi[ch];
        const bf16* al = Alo[ch];
#pragma unroll
        for (int rep = 0; rep < 4; rep++) {
            int u = rep * 256 + tid;
            int r = u >> 3, j = u & 7;
            int grow = rowBase + r;
            uint4 vh = make_uint4(0, 0, 0, 0), vl = vh;
            if (grow < NN) {
                vh = *(const uint4*)(ah + (size_t)grow * FF + j * 8);
                vl = *(const uint4*)(al + (size_t)grow * FF + j * 8);
            }
            *(uint4*)(smem + OFF_AH + r * 144 + j * 16) = vh;
            *(uint4*)(smem + OFF_AL + r * 144 + j * 16) = vl;
            // stage B hi/lo: col=r, k slice [ch*64, ch*64+64)
            uint4 bh = *(const uint4*)(g_Bhi + r * 256 + ch * 64 + j * 8);
            uint4 bl = *(const uint4*)(g_Blo + r * 256 + ch * 64 + j * 8);
            *(uint4*)(smem + OFF_BH + r * 144 + j * 16) = bh;
            *(uint4*)(smem + OFF_BL + r * 144 + j * 16) = bl;
        }
        __syncthreads();

#pragma unroll
        for (int ks = 0; ks < 4; ks++) {
            int k0 = ks * 16;
            uint32_t af[4][4], bh[4][2], bl[4][2];
#pragma unroll
            for (int mt = 0; mt < 4; mt++) {
                int r = wm * 64 + mt * 16 + g;
                const char* p = smem + OFF_AH;
                af[mt][0] = *(const uint32_t*)(p + (r * SA + k0 + t * 2) * 2);
                af[mt][1] = *(const uint32_t*)(p + ((r + 8) * SA + k0 + t * 2) * 2);
                af[mt][2] = *(const uint32_t*)(p + (r * SA + k0 + t * 2 + 8) * 2);
                af[mt][3] = *(const uint32_t*)(p + ((r + 8) * SA + k0 + t * 2 + 8) * 2);
            }
#pragma unroll
            for (int nt = 0; nt < 4; nt++) {
                int c = wn * 32 + nt * 8 + g;
                bh[nt][0] = *(const uint32_t*)(smem + OFF_BH + (c * SA + k0 + t * 2) * 2);
                bh[nt][1] = *(const uint32_t*)(smem + OFF_BH + (c * SA + k0 + t * 2 + 8) * 2);
                bl[nt][0] = *(const uint32_t*)(smem + OFF_BL + (c * SA + k0 + t * 2) * 2);
                bl[nt][1] = *(const uint32_t*)(smem + OFF_BL + (c * SA + k0 + t * 2 + 8) * 2);
            }
            // Ahi * Bhi
#pragma unroll
            for (int mt = 0; mt < 4; mt++)
#pragma unroll
                for (int nt = 0; nt < 4; nt++)
                    mma16816(acc[mt][nt][0], acc[mt][nt][1], acc[mt][nt][2], acc[mt][nt][3],
                             af[mt][0], af[mt][1], af[mt][2], af[mt][3],
                             bh[nt][0], bh[nt][1]);
            // Ahi * Blo
#pragma unroll
            for (int mt = 0; mt < 4; mt++)
#pragma unroll
                for (int nt = 0; nt < 4; nt++)
                    mma16816(acc[mt][nt][0], acc[mt][nt][1], acc[mt][nt][2], acc[mt][nt][3],
                             af[mt][0], af[mt][1], af[mt][2], af[mt][3],
                             bl[nt][0], bl[nt][1]);
            // Alo * Bhi (reload A frags from lo plane)
#pragma unroll
            for (int mt = 0; mt < 4; mt++) {
                int r = wm * 64 + mt * 16 + g;
                const char* p = smem + OFF_AL;
                af[mt][0] = *(const uint32_t*)(p + (r * SA + k0 + t * 2) * 2);
                af[mt][1] = *(const uint32_t*)(p + ((r + 8) * SA + k0 + t * 2) * 2);
                af[mt][2] = *(const uint32_t*)(p + (r * SA + k0 + t * 2 + 8) * 2);
                af[mt][3] = *(const uint32_t*)(p + ((r + 8) * SA + k0 + t * 2 + 8) * 2);
            }
#pragma unroll
            for (int mt = 0; mt < 4; mt++)
#pragma unroll
                for (int nt = 0; nt < 4; nt++)
                    mma16816(acc[mt][nt][0], acc[mt][nt][1], acc[mt][nt][2], acc[mt][nt][3],
                             af[mt][0], af[mt][1], af[mt][2], af[mt][3],
                             bh[nt][0], bh[nt][1]);
        }
    }
    __syncthreads();

    // epilogue: tanh(acc + bias) * fw, reduce cols -> sm_out rows
    const float* sBias = (const float*)(smem + OFF_BIAS);
    const float* sFw   = (const float*)(smem + OFF_FW);
    float* sOut        = (float*)(smem + OFF_OUT);
#pragma unroll
    for (int mt = 0; mt < 4; mt++) {
#pragma unroll
        for (int rr = 0; rr < 2; rr++) {
            int rloc = wm * 64 + mt * 16 + g + rr * 8;
            float p = 0.f;
#pragma unroll
            for (int nt = 0; nt < 4; nt++) {
#pragma unroll
                for (int cc = 0; cc < 2; cc++) {
                    int col = wn * 32 + nt * 8 + t * 2 + cc;
                    float v = acc[mt][nt][rr * 2 + cc];
                    p += tanh_ap(v + sBias[col]) * sFw[col];
                }
            }
            p += __shfl_xor_sync(0xffffffffu, p, 1);
            p += __shfl_xor_sync(0xffffffffu, p, 2);
            if (t == 0) atomicAdd(&sOut[rloc], p);
        }
    }
    __syncthreads();
    if (tid < 128) {
        int r = rowBase + tid;
        if (r < NN) y[r] = sOut[tid] + fb[0];
    }
}

// ---------------- launch -----------------------------------------------------
extern "C" void kernel_launch(void* const* d_in, const int* in_sizes, int n_in,
                              void* d_out, int out_size) {
    const float* features = (const float*)d_in[0];
    const int*   ei       = (const int*)d_in[1];
    const float* cheb_w   = (const float*)d_in[2];
    const float* cheb_b   = (const float*)d_in[3];
    const float* final_w  = (const float*)d_in[4];
    const float* final_b  = (const float*)d_in[5];
    float* y = (float*)d_out;

    static bool attr_set = false;
    if (!attr_set) {
        cudaFuncSetAttribute(k_gemm, cudaFuncAttributeMaxDynamicSharedMemorySize,
                             SMEM_DYN);
        attr_set = true;
    }

    k_zero_cnt<<<(NN + 255) / 256, 256>>>();
    k_fill<<<(EE + 255) / 256, 256>>>(ei);
    k_prep<<<SCALE_BLOCKS + 128, 256>>>(features, cheb_w);

    int spmm_blocks = (NN + 7) / 8;          // 8 warp-rows per 256-thread block
    k_spmm<1><<<spmm_blocks, 256>>>(features);   // profiled slot (idx 3)
    k_spmm<2><<<spmm_blocks, 256>>>(features);
    k_spmm<3><<<spmm_blocks, 256>>>(features);

    k_gemm<<<(NN + 127) / 128, 256, SMEM_DYN>>>(cheb_b, final_w, final_b, y);
}

// round 5
// speedup vs baseline: 1.2961x; 1.0017x over previous
#include <cuda_runtime.h>
#include <cuda_bf16.h>
#include <cstdint>

// Problem constants (fixed by the dataset)
#define NN 50000
#define EE 800000
#define FF 64
#define HH 128
#define CAP 96   // ELL capacity per row; deg ~ Poisson(16), P(deg>96) ~ 0

typedef unsigned long long ull;
typedef __nv_bfloat16 bf16;

// ---------------- scratch (static device globals; no allocations) -----------
__device__ int   g_cnt[NN];
__device__ float g_dinv[NN];
__device__ int   g_ell[(size_t)NN * CAP];   // PRE-SHIFTED: col*FF element offset
__device__ float g_XS [(size_t)NN * FF];    // dinv * X
__device__ float g_T1 [(size_t)NN * FF];    // f32 T1 (prev for phase 3)
__device__ float g_T1S[(size_t)NN * FF];
__device__ float g_T2S[(size_t)NN * FF];
// bf16 hi/lo planes consumed by the HMMA GEMM
__device__ bf16 g_Xhi [(size_t)NN * FF];
__device__ bf16 g_Xlo [(size_t)NN * FF];
__device__ bf16 g_T1hi[(size_t)NN * FF];
__device__ bf16 g_T1lo[(size_t)NN * FF];
__device__ bf16 g_T2hi[(size_t)NN * FF];
__device__ bf16 g_T2lo[(size_t)NN * FF];
__device__ bf16 g_T3hi[(size_t)NN * FF];
__device__ bf16 g_T3lo[(size_t)NN * FF];
__device__ bf16 g_Bhi[128 * 256];           // B^T hi  [h][kidx]
__device__ bf16 g_Blo[128 * 256];           // B^T lo

// ---------------- helpers ----------------------------------------------------
__device__ __forceinline__ float tanh_ap(float x) {
    float r;
    asm("tanh.approx.f32 %0, %1;" : "=f"(r) : "f"(x));
    return r;
}
__device__ __forceinline__ ull add2(ull a, ull b) {
    ull d;
    asm("add.rn.f32x2 %0, %1, %2;" : "=l"(d) : "l"(a), "l"(b));
    return d;
}
__device__ __forceinline__ void upk2(ull v, float& lo, float& hi) {
    asm("mov.b64 {%0, %1}, %2;" : "=f"(lo), "=f"(hi) : "l"(v));
}

__device__ __forceinline__ void mma16816(float& d0, float& d1, float& d2, float& d3,
                                         uint32_t a0, uint32_t a1, uint32_t a2, uint32_t a3,
                                         uint32_t b0, uint32_t b1) {
    asm volatile(
        "mma.sync.aligned.m16n8k16.row.col.f32.bf16.bf16.f32 "
        "{%0,%1,%2,%3}, {%4,%5,%6,%7}, {%8,%9}, {%0,%1,%2,%3};"
        : "+f"(d0), "+f"(d1), "+f"(d2), "+f"(d3)
        : "r"(a0), "r"(a1), "r"(a2), "r"(a3), "r"(b0), "r"(b1));
}

// split f32 pair -> packed bf16x2 hi and lo
__device__ __forceinline__ void split_hilo(float x, float y,
                                           uint32_t& hp, uint32_t& lp) {
    bf16 h0 = __float2bfloat16(x), h1 = __float2bfloat16(y);
    bf16 l0 = __float2bfloat16(x - __bfloat162float(h0));
    bf16 l1 = __float2bfloat16(y - __bfloat162float(h1));
    hp = (uint32_t)__bfloat16_as_ushort(h0) | ((uint32_t)__bfloat16_as_ushort(h1) << 16);
    lp = (uint32_t)__bfloat16_as_ushort(l0) | ((uint32_t)__bfloat16_as_ushort(l1) << 16);
}

// ---------------- graph build ------------------------------------------------
__global__ void k_zero_cnt() {
    int i = blockIdx.x * blockDim.x + threadIdx.x;
    if (i < NN) g_cnt[i] = 0;
}

__global__ void k_fill(const int* __restrict__ ei) {
    int e = blockIdx.x * blockDim.x + threadIdx.x;
    if (e >= EE) return;
    int r = ei[e];
    int c = ei[EE + e];
    int s = atomicAdd(&g_cnt[r], 1);
    if (s < CAP) g_ell[(size_t)r * CAP + s] = c * FF;   // pre-shifted offset
}

// combo: blocks [0, 6250): dinv + XS = dinv*X + X hi/lo planes (warp per row)
//        blocks [6250, 6378): B^T hi/lo precompute from cheb_w
#define SCALE_BLOCKS 6250
__global__ void k_prep(const float* __restrict__ x, const float* __restrict__ W) {
    int tid = threadIdx.x;
    if (blockIdx.x < SCALE_BLOCKS) {
        int row  = blockIdx.x * 8 + (tid >> 5);
        int lane = tid & 31;
        int cnt = g_cnt[row];
        float d = (cnt > 0) ? rsqrtf((float)cnt) : 0.0f;
        if (lane == 0) g_dinv[row] = d;
        int l2 = lane * 2;
        size_t idx = (size_t)row * FF + l2;
        float2 v = *(const float2*)(x + idx);
        uint32_t hp, lp;
        split_hilo(v.x, v.y, hp, lp);
        *(uint32_t*)(g_Xhi + idx) = hp;
        *(uint32_t*)(g_Xlo + idx) = lp;
        v.x *= d; v.y *= d;
        *(float2*)(g_XS + idx) = v;
    } else {
        int idx = (blockIdx.x - SCALE_BLOCKS) * 256 + tid;  // 0..32767
        int h = idx >> 8, kidx = idx & 255;
        int k4 = kidx >> 6, f = kidx & 63;
        float w = W[k4 * (FF * HH) + f * HH + h];
        bf16 hi = __float2bfloat16(w);
        bf16 lo = __float2bfloat16(w - __bfloat162float(hi));
        g_Bhi[h * 256 + kidx] = hi;
        g_Blo[h * 256 + kidx] = lo;
    }
}

// ---------------- SPMM: warp per row, weight-free gather of pre-scaled src ---
// spmm(z)[r] = -dinv[r] * sum_{c in N(r)} (dinv*z)[c]
// Packed f32x2 accumulation; ELL entries are pre-shifted element offsets.
template <int PHASE>
__global__ void k_spmm(const float* __restrict__ x) {
    int row  = (blockIdx.x * blockDim.x + threadIdx.x) >> 5;
    int lane = threadIdx.x & 31;
    if (row >= NN) return;
    int l2 = lane * 2;

    const float* __restrict__ srcS = (PHASE == 1) ? g_XS
                                   : (PHASE == 2) ? g_T1S : g_T2S;
    const float* __restrict__ prev = (PHASE == 2) ? x
                                   : (PHASE == 3) ? g_T1 : nullptr;
    bf16* __restrict__ dhi = (PHASE == 1) ? g_T1hi
                           : (PHASE == 2) ? g_T2hi : g_T3hi;
    bf16* __restrict__ dlo = (PHASE == 1) ? g_T1lo
                           : (PHASE == 2) ? g_T2lo : g_T3lo;

    float d = g_dinv[row];                    // early, hides latency
    int cnt = g_cnt[row]; if (cnt > CAP) cnt = CAP;
    const int* ep = g_ell + (size_t)row * CAP;
    const float* srcL = srcS + l2;            // lane-adjusted base

    ull accA = 0ull, accB = 0ull;
    int i = 0;
    int n8 = cnt & ~7;
    for (; i < n8; i += 8) {
        int4 ca = *(const int4*)(ep + i);
        int4 cb = *(const int4*)(ep + i + 4);
        ull v0 = *(const ull*)(srcL + ca.x);
        ull v1 = *(const ull*)(srcL + ca.y);
        ull v2 = *(const ull*)(srcL + ca.z);
        ull v3 = *(const ull*)(srcL + ca.w);
        ull v4 = *(const ull*)(srcL + cb.x);
        ull v5 = *(const ull*)(srcL + cb.y);
        ull v6 = *(const ull*)(srcL + cb.z);
        ull v7 = *(const ull*)(srcL + cb.w);
        accA = add2(accA, add2(add2(v0, v1), add2(v2, v3)));
        accB = add2(accB, add2(add2(v4, v5), add2(v6, v7)));
    }
    int n4 = cnt & ~3;
    for (; i < n4; i += 4) {
        int4 ca = *(const int4*)(ep + i);
        ull v0 = *(const ull*)(srcL + ca.x);
        ull v1 = *(const ull*)(srcL + ca.y);
        ull v2 = *(const ull*)(srcL + ca.z);
        ull v3 = *(const ull*)(srcL + ca.w);
        accA = add2(accA, add2(v0, v1));
        accB = add2(accB, add2(v2, v3));
    }
    for (; i < cnt; i++) {
        accA = add2(accA, *(const ull*)(srcL + ep[i]));
    }
    ull acc = add2(accA, accB);
    float ax, ay;
    upk2(acc, ax, ay);

    size_t idx = (size_t)row * FF + l2;
    float2 res;
    if (PHASE == 1) {
        res.x = -d * ax;
        res.y = -d * ay;
        *(float2*)(g_T1 + idx) = res;                // needed as prev in phase 3
    } else {
        float2 p = *(const float2*)(prev + idx);
        float m = -2.f * d;
        res.x = fmaf(m, ax, -p.x);
        res.y = fmaf(m, ay, -p.y);
    }
    uint32_t hp, lp;
    split_hilo(res.x, res.y, hp, lp);
    *(uint32_t*)(dhi + idx) = hp;
    *(uint32_t*)(dlo + idx) = lp;
    if (PHASE <= 2) {
        float* dstS = (PHASE == 1) ? g_T1S : g_T2S;
        float2 rs; rs.x = d * res.x; rs.y = d * res.y;
        *(float2*)(dstS + idx) = rs;
    }
}

// ---------------- HMMA GEMM + bias + tanh + final dot ------------------------
// out[n,h] = sum_k [X|T1|T2|T3][n,:] @ W[:,h] + b[h]; y[n]=sum_h tanh(out)*fw+fb
// bf16 hi/lo split: AhiBhi + AhiBlo + AloBhi.
// CTA tile 128 rows x 128 h, K in 4 chunks of 64 (chunk == source matrix).
// Warp grid 2(m) x 4(n): warp tile 64x32 via m16n8k16 (4 m-tiles x 4 n-tiles).
#define SA 72                      // smem row stride in elements (144 B)
#define OFF_AH 0
#define OFF_AL (128 * SA * 2)      // 18432
#define OFF_BH (2 * 128 * SA * 2)
#define OFF_BL (3 * 128 * SA * 2)
#define OFF_BIAS (4 * 128 * SA * 2)        // 73728
#define OFF_FW   (OFF_BIAS + 512)
#define OFF_OUT  (OFF_FW + 512)
#define SMEM_DYN (OFF_OUT + 512)

__global__ __launch_bounds__(256)
void k_gemm(const float* __restrict__ bias, const float* __restrict__ fw,
            const float* __restrict__ fb, float* __restrict__ y) {
    extern __shared__ char smem[];
    int tid  = threadIdx.x;
    int lane = tid & 31, wid = tid >> 5;
    int wm = wid >> 2, wn = wid & 3;        // warp grid 2x4
    int g = lane >> 2, t = lane & 3;        // mma groupID / threadID-in-group
    int rowBase = blockIdx.x * 128;

    if (tid < 128) {
        *(float*)(smem + OFF_BIAS + tid * 4) = bias[tid];
        *(float*)(smem + OFF_FW   + tid * 4) = fw[tid];
        *(float*)(smem + OFF_OUT  + tid * 4) = 0.f;
    }

    float acc[4][4][4];
#pragma unroll
    for (int a = 0; a < 4; a++)
#pragma unroll
        for (int b = 0; b < 4; b++)
#pragma unroll
            for (int c = 0; c < 4; c++) acc[a][b][c] = 0.f;

    const bf16* Ahi[4] = {g_Xhi, g_T1hi, g_T2hi, g_T3hi};
    const bf16* Alo[4] = {g_Xlo, g_T1lo, g_T2lo, g_T3lo};

    for (int ch = 0; ch < 4; ch++) {
        __syncthreads();
        const bf16* ah = Ahi[ch];
        const bf16* al = Alo[ch];
#pragma unroll
        for (int rep = 0; rep < 4; rep++) {
            int u = rep * 256 + tid;
            int r = u >> 3, j = u & 7;
            int grow = rowBase + r;
            uint4 vh = make_uint4(0, 0, 0, 0), vl = vh;
            if (grow < NN) {
                vh = *(const uint4*)(ah + (size_t)grow * FF + j * 8);
                vl = *(const uint4*)(al + (size_t)grow * FF + j * 8);
            }
            *(uint4*)(smem + OFF_AH + r * 144 + j * 16) = vh;
            *(uint4*)(smem + OFF_AL + r * 144 + j * 16) = vl;
            uint4 bh = *(const uint4*)(g_Bhi + r * 256 + ch * 64 + j * 8);
            uint4 bl = *(const uint4*)(g_Blo + r * 256 + ch * 64 + j * 8);
            *(uint4*)(smem + OFF_BH + r * 144 + j * 16) = bh;
            *(uint4*)(smem + OFF_BL + r * 144 + j * 16) = bl;
        }
        __syncthreads();

#pragma unroll
        for (int ks = 0; ks < 4; ks++) {
            int k0 = ks * 16;
            uint32_t af[4][4], bh[4][2], bl[4][2];
#pragma unroll
            for (int mt = 0; mt < 4; mt++) {
                int r = wm * 64 + mt * 16 + g;
                const char* p = smem + OFF_AH;
                af[mt][0] = *(const uint32_t*)(p + (r * SA + k0 + t * 2) * 2);
                af[mt][1] = *(const uint32_t*)(p + ((r + 8) * SA + k0 + t * 2) * 2);
                af[mt][2] = *(const uint32_t*)(p + (r * SA + k0 + t * 2 + 8) * 2);
                af[mt][3] = *(const uint32_t*)(p + ((r + 8) * SA + k0 + t * 2 + 8) * 2);
            }
#pragma unroll
            for (int nt = 0; nt < 4; nt++) {
                int c = wn * 32 + nt * 8 + g;
                bh[nt][0] = *(const uint32_t*)(smem + OFF_BH + (c * SA + k0 + t * 2) * 2);
                bh[nt][1] = *(const uint32_t*)(smem + OFF_BH + (c * SA + k0 + t * 2 + 8) * 2);
                bl[nt][0] = *(const uint32_t*)(smem + OFF_BL + (c * SA + k0 + t * 2) * 2);
                bl[nt][1] = *(const uint32_t*)(smem + OFF_BL + (c * SA + k0 + t * 2 + 8) * 2);
            }
#pragma unroll
            for (int mt = 0; mt < 4; mt++)
#pragma unroll
                for (int nt = 0; nt < 4; nt++)
                    mma16816(acc[mt][nt][0], acc[mt][nt][1], acc[mt][nt][2], acc[mt][nt][3],
                             af[mt][0], af[mt][1], af[mt][2], af[mt][3],
                             bh[nt][0], bh[nt][1]);
#pragma unroll
            for (int mt = 0; mt < 4; mt++)
#pragma unroll
                for (int nt = 0; nt < 4; nt++)
                    mma16816(acc[mt][nt][0], acc[mt][nt][1], acc[mt][nt][2], acc[mt][nt][3],
                             af[mt][0], af[mt][1], af[mt][2], af[mt][3],
                             bl[nt][0], bl[nt][1]);
#pragma unroll
            for (int mt = 0; mt < 4; mt++) {
                int r = wm * 64 + mt * 16 + g;
                const char* p = smem + OFF_AL;
                af[mt][0] = *(const uint32_t*)(p + (r * SA + k0 + t * 2) * 2);
                af[mt][1] = *(const uint32_t*)(p + ((r + 8) * SA + k0 + t * 2) * 2);
                af[mt][2] = *(const uint32_t*)(p + (r * SA + k0 + t * 2 + 8) * 2);
                af[mt][3] = *(const uint32_t*)(p + ((r + 8) * SA + k0 + t * 2 + 8) * 2);
            }
#pragma unroll
            for (int mt = 0; mt < 4; mt++)
#pragma unroll
                for (int nt = 0; nt < 4; nt++)
                    mma16816(acc[mt][nt][0], acc[mt][nt][1], acc[mt][nt][2], acc[mt][nt][3],
                             af[mt][0], af[mt][1], af[mt][2], af[mt][3],
                             bh[nt][0], bh[nt][1]);
        }
    }
    __syncthreads();

    // epilogue: tanh(acc + bias) * fw, reduce cols -> sm_out rows
    const float* sBias = (const float*)(smem + OFF_BIAS);
    const float* sFw   = (const float*)(smem + OFF_FW);
    float* sOut        = (float*)(smem + OFF_OUT);
#pragma unroll
    for (int mt = 0; mt < 4; mt++) {
#pragma unroll
        for (int rr = 0; rr < 2; rr++) {
            int rloc = wm * 64 + mt * 16 + g + rr * 8;
            float p = 0.f;
#pragma unroll
            for (int nt = 0; nt < 4; nt++) {
#pragma unroll
                for (int cc = 0; cc < 2; cc++) {
                    int col = wn * 32 + nt * 8 + t * 2 + cc;
                    float v = acc[mt][nt][rr * 2 + cc];
                    p += tanh_ap(v + sBias[col]) * sFw[col];
                }
            }
            p += __shfl_xor_sync(0xffffffffu, p, 1);
            p += __shfl_xor_sync(0xffffffffu, p, 2);
            if (t == 0) atomicAdd(&sOut[rloc], p);
        }
    }
    __syncthreads();
    if (tid < 128) {
        int r = rowBase + tid;
        if (r < NN) y[r] = sOut[tid] + fb[0];
    }
}

// ---------------- launch -----------------------------------------------------
extern "C" void kernel_launch(void* const* d_in, const int* in_sizes, int n_in,
                              void* d_out, int out_size) {
    const float* features = (const float*)d_in[0];
    const int*   ei       = (const int*)d_in[1];
    const float* cheb_w   = (const float*)d_in[2];
    const float* cheb_b   = (const float*)d_in[3];
    const float* final_w  = (const float*)d_in[4];
    const float* final_b  = (const float*)d_in[5];
    float* y = (float*)d_out;

    static bool attr_set = false;
    if (!attr_set) {
        cudaFuncSetAttribute(k_gemm, cudaFuncAttributeMaxDynamicSharedMemorySize,
                             SMEM_DYN);
        attr_set = true;
    }

    k_zero_cnt<<<(NN + 255) / 256, 256>>>();
    k_fill<<<(EE + 255) / 256, 256>>>(ei);
    k_prep<<<SCALE_BLOCKS + 128, 256>>>(features, cheb_w);

    int spmm_blocks = (NN + 7) / 8;          // 8 warp-rows per 256-thread block
    k_spmm<1><<<spmm_blocks, 256>>>(features);
    k_spmm<2><<<spmm_blocks, 256>>>(features);
    k_spmm<3><<<spmm_blocks, 256>>>(features);

    k_gemm<<<(NN + 127) / 128, 256, SMEM_DYN>>>(cheb_b, final_w, final_b, y);
}

// round 6
// speedup vs baseline: 1.4104x; 1.0882x over previous
#include <cuda_runtime.h>
#include <cuda_bf16.h>
#include <cstdint>

// Problem constants (fixed by the dataset)
#define NN 50000
#define EE 800000
#define FF 64
#define HH 128
#define CAP 96   // ELL capacity per row; deg ~ Poisson(16), P(deg>96) ~ 0

typedef unsigned long long ull;
typedef __nv_bfloat16 bf16;

// ---------------- scratch (static device globals; no allocations) -----------
__device__ int   g_cnt[NN];                 // zero-init at load; re-zeroed by k_gemm
__device__ float g_dinv[NN];
__device__ int   g_ell[(size_t)NN * CAP];   // PRE-SHIFTED: col*FF element offset
__device__ float g_XS [(size_t)NN * FF];    // dinv * X
__device__ float g_T1S[(size_t)NN * FF];    // dinv * T1
__device__ float g_T2S[(size_t)NN * FF];    // dinv * T2
// bf16 hi/lo planes: GEMM inputs AND the 'prev' source for the recursion
__device__ bf16 g_Xhi [(size_t)NN * FF];
__device__ bf16 g_Xlo [(size_t)NN * FF];
__device__ bf16 g_T1hi[(size_t)NN * FF];
__device__ bf16 g_T1lo[(size_t)NN * FF];
__device__ bf16 g_T2hi[(size_t)NN * FF];
__device__ bf16 g_T2lo[(size_t)NN * FF];
__device__ bf16 g_T3hi[(size_t)NN * FF];
__device__ bf16 g_T3lo[(size_t)NN * FF];
__device__ bf16 g_Bhi[128 * 256];           // B^T hi  [h][kidx]
__device__ bf16 g_Blo[128 * 256];           // B^T lo

// ---------------- helpers ----------------------------------------------------
__device__ __forceinline__ float tanh_ap(float x) {
    float r;
    asm("tanh.approx.f32 %0, %1;" : "=f"(r) : "f"(x));
    return r;
}
__device__ __forceinline__ ull add2(ull a, ull b) {
    ull d;
    asm("add.rn.f32x2 %0, %1, %2;" : "=l"(d) : "l"(a), "l"(b));
    return d;
}
__device__ __forceinline__ void upk2(ull v, float& lo, float& hi) {
    asm("mov.b64 {%0, %1}, %2;" : "=f"(lo), "=f"(hi) : "l"(v));
}

__device__ __forceinline__ void mma16816(float& d0, float& d1, float& d2, float& d3,
                                         uint32_t a0, uint32_t a1, uint32_t a2, uint32_t a3,
                                         uint32_t b0, uint32_t b1) {
    asm volatile(
        "mma.sync.aligned.m16n8k16.row.col.f32.bf16.bf16.f32 "
        "{%0,%1,%2,%3}, {%4,%5,%6,%7}, {%8,%9}, {%0,%1,%2,%3};"
        : "+f"(d0), "+f"(d1), "+f"(d2), "+f"(d3)
        : "r"(a0), "r"(a1), "r"(a2), "r"(a3), "r"(b0), "r"(b1));
}

// split f32 pair -> packed bf16x2 hi and lo
__device__ __forceinline__ void split_hilo(float x, float y,
                                           uint32_t& hp, uint32_t& lp) {
    bf16 h0 = __float2bfloat16(x), h1 = __float2bfloat16(y);
    bf16 l0 = __float2bfloat16(x - __bfloat162float(h0));
    bf16 l1 = __float2bfloat16(y - __bfloat162float(h1));
    hp = (uint32_t)__bfloat16_as_ushort(h0) | ((uint32_t)__bfloat16_as_ushort(h1) << 16);
    lp = (uint32_t)__bfloat16_as_ushort(l0) | ((uint32_t)__bfloat16_as_ushort(l1) << 16);
}

// ---------------- graph build ------------------------------------------------
// NOTE: g_cnt is zero on entry to every call: zero-initialized at module load,
// and re-zeroed at the head of k_gemm (which runs after all g_cnt consumers).
__global__ void k_fill(const int* __restrict__ ei) {
    int e = blockIdx.x * blockDim.x + threadIdx.x;
    if (e >= EE) return;
    int r = ei[e];
    int c = ei[EE + e];
    int s = atomicAdd(&g_cnt[r], 1);
    if (s < CAP) g_ell[(size_t)r * CAP + s] = c * FF;   // pre-shifted offset
}

// combo: blocks [0, 6250): dinv + XS = dinv*X + X hi/lo planes (warp per row)
//        blocks [6250, 6378): B^T hi/lo precompute from cheb_w
#define SCALE_BLOCKS 6250
__global__ void k_prep(const float* __restrict__ x, const float* __restrict__ W) {
    int tid = threadIdx.x;
    if (blockIdx.x < SCALE_BLOCKS) {
        int row  = blockIdx.x * 8 + (tid >> 5);
        int lane = tid & 31;
        int cnt = g_cnt[row];
        float d = (cnt > 0) ? rsqrtf((float)cnt) : 0.0f;
        if (lane == 0) g_dinv[row] = d;
        int l2 = lane * 2;
        size_t idx = (size_t)row * FF + l2;
        float2 v = *(const float2*)(x + idx);
        uint32_t hp, lp;
        split_hilo(v.x, v.y, hp, lp);
        *(uint32_t*)(g_Xhi + idx) = hp;
        *(uint32_t*)(g_Xlo + idx) = lp;
        v.x *= d; v.y *= d;
        *(float2*)(g_XS + idx) = v;
    } else {
        int idx = (blockIdx.x - SCALE_BLOCKS) * 256 + tid;  // 0..32767
        int h = idx >> 8, kidx = idx & 255;
        int k4 = kidx >> 6, f = kidx & 63;
        float w = W[k4 * (FF * HH) + f * HH + h];
        bf16 hi = __float2bfloat16(w);
        bf16 lo = __float2bfloat16(w - __bfloat162float(hi));
        g_Bhi[h * 256 + kidx] = hi;
        g_Blo[h * 256 + kidx] = lo;
    }
}

// ---------------- SPMM: warp per row, weight-free gather of pre-scaled src ---
// spmm(z)[r] = -dinv[r] * sum_{c in N(r)} (dinv*z)[c]
// prev terms reconstructed from bf16 hi/lo planes (err ~2^-17).
template <int PHASE>
__global__ __launch_bounds__(256, 8)
void k_spmm() {
    int row  = (blockIdx.x * blockDim.x + threadIdx.x) >> 5;
    int lane = threadIdx.x & 31;
    if (row >= NN) return;
    int l2 = lane * 2;

    const float* __restrict__ srcS = (PHASE == 1) ? g_XS
                                   : (PHASE == 2) ? g_T1S : g_T2S;
    const bf16* __restrict__ phi = (PHASE == 2) ? g_Xhi : g_T1hi;
    const bf16* __restrict__ plo = (PHASE == 2) ? g_Xlo : g_T1lo;
    bf16* __restrict__ dhi = (PHASE == 1) ? g_T1hi
                           : (PHASE == 2) ? g_T2hi : g_T3hi;
    bf16* __restrict__ dlo = (PHASE == 1) ? g_T1lo
                           : (PHASE == 2) ? g_T2lo : g_T3lo;

    float d = g_dinv[row];                    // early, hides latency
    int cnt = g_cnt[row]; if (cnt > CAP) cnt = CAP;
    const int* ep = g_ell + (size_t)row * CAP;
    const float* srcL = srcS + l2;            // lane-adjusted base

    ull accA = 0ull, accB = 0ull;
    int i = 0;
    int n8 = cnt & ~7;
    for (; i < n8; i += 8) {
        int4 ca = *(const int4*)(ep + i);
        int4 cb = *(const int4*)(ep + i + 4);
        ull v0 = *(const ull*)(srcL + ca.x);
        ull v1 = *(const ull*)(srcL + ca.y);
        ull v2 = *(const ull*)(srcL + ca.z);
        ull v3 = *(const ull*)(srcL + ca.w);
        ull v4 = *(const ull*)(srcL + cb.x);
        ull v5 = *(const ull*)(srcL + cb.y);
        ull v6 = *(const ull*)(srcL + cb.z);
        ull v7 = *(const ull*)(srcL + cb.w);
        accA = add2(accA, add2(add2(v0, v1), add2(v2, v3)));
        accB = add2(accB, add2(add2(v4, v5), add2(v6, v7)));
    }
    int n4 = cnt & ~3;
    for (; i < n4; i += 4) {
        int4 ca = *(const int4*)(ep + i);
        ull v0 = *(const ull*)(srcL + ca.x);
        ull v1 = *(const ull*)(srcL + ca.y);
        ull v2 = *(const ull*)(srcL + ca.z);
        ull v3 = *(const ull*)(srcL + ca.w);
        accA = add2(accA, add2(v0, v1));
        accB = add2(accB, add2(v2, v3));
    }
    for (; i < cnt; i++) {
        accA = add2(accA, *(const ull*)(srcL + ep[i]));
    }
    ull acc = add2(accA, accB);
    float ax, ay;
    upk2(acc, ax, ay);

    size_t idx = (size_t)row * FF + l2;
    float2 res;
    if (PHASE == 1) {
        res.x = -d * ax;
        res.y = -d * ay;
    } else {
        float2 ph = __bfloat1622float2(*(const __nv_bfloat162*)(phi + idx));
        float2 pl = __bfloat1622float2(*(const __nv_bfloat162*)(plo + idx));
        float m = -2.f * d;
        res.x = fmaf(m, ax, -(ph.x + pl.x));
        res.y = fmaf(m, ay, -(ph.y + pl.y));
    }
    uint32_t hp, lp;
    split_hilo(res.x, res.y, hp, lp);
    *(uint32_t*)(dhi + idx) = hp;
    *(uint32_t*)(dlo + idx) = lp;
    if (PHASE <= 2) {
        float* dstS = (PHASE == 1) ? g_T1S : g_T2S;
        float2 rs; rs.x = d * res.x; rs.y = d * res.y;
        *(float2*)(dstS + idx) = rs;
    }
}

// ---------------- HMMA GEMM + bias + tanh + final dot ------------------------
// out[n,h] = sum_k [X|T1|T2|T3][n,:] @ W[:,h] + b[h]; y[n]=sum_h tanh(out)*fw+fb
// bf16 hi/lo split: AhiBhi + AhiBlo + AloBhi.
// CTA tile 128 rows x 128 h, K in 4 chunks of 64 (chunk == source matrix).
// Warp grid 2(m) x 4(n): warp tile 64x32 via m16n8k16 (4 m-tiles x 4 n-tiles).
// ALSO: re-zeros g_cnt for the next kernel_launch call (graph replay invariant).
#define SA 72                      // smem row stride in elements (144 B)
#define OFF_AH 0
#define OFF_AL (128 * SA * 2)      // 18432
#define OFF_BH (2 * 128 * SA * 2)
#define OFF_BL (3 * 128 * SA * 2)
#define OFF_BIAS (4 * 128 * SA * 2)        // 73728
#define OFF_FW   (OFF_BIAS + 512)
#define OFF_OUT  (OFF_FW + 512)
#define SMEM_DYN (OFF_OUT + 512)

__global__ __launch_bounds__(256)
void k_gemm(const float* __restrict__ bias, const float* __restrict__ fw,
            const float* __restrict__ fb, float* __restrict__ y) {
    extern __shared__ char smem[];
    int tid  = threadIdx.x;
    int lane = tid & 31, wid = tid >> 5;
    int wm = wid >> 2, wn = wid & 3;        // warp grid 2x4
    int g = lane >> 2, t = lane & 3;        // mma groupID / threadID-in-group
    int rowBase = blockIdx.x * 128;

    // re-zero g_cnt for next call (g_cnt consumers all ran earlier this call)
    int zi = blockIdx.x * 256 + tid;
    if (zi < NN) g_cnt[zi] = 0;

    if (tid < 128) {
        *(float*)(smem + OFF_BIAS + tid * 4) = bias[tid];
        *(float*)(smem + OFF_FW   + tid * 4) = fw[tid];
        *(float*)(smem + OFF_OUT  + tid * 4) = 0.f;
    }

    float acc[4][4][4];
#pragma unroll
    for (int a = 0; a < 4; a++)
#pragma unroll
        for (int b = 0; b < 4; b++)
#pragma unroll
            for (int c = 0; c < 4; c++) acc[a][b][c] = 0.f;

    const bf16* Ahi[4] = {g_Xhi, g_T1hi, g_T2hi, g_T3hi};
    const bf16* Alo[4] = {g_Xlo, g_T1lo, g_T2lo, g_T3lo};

    for (int ch = 0; ch < 4; ch++) {
        __syncthreads();
        const bf16* ah = Ahi[ch];
        const bf16* al = Alo[ch];
#pragma unroll
        for (int rep = 0; rep < 4; rep++) {
            int u = rep * 256 + tid;
            int r = u >> 3, j = u & 7;
            int grow = rowBase + r;
            uint4 vh = make_uint4(0, 0, 0, 0), vl = vh;
            if (grow < NN) {
                vh = *(const uint4*)(ah + (size_t)grow * FF + j * 8);
                vl = *(const uint4*)(al + (size_t)grow * FF + j * 8);
            }
            *(uint4*)(smem + OFF_AH + r * 144 + j * 16) = vh;
            *(uint4*)(smem + OFF_AL + r * 144 + j * 16) = vl;
            uint4 bh = *(const uint4*)(g_Bhi + r * 256 + ch * 64 + j * 8);
            uint4 bl = *(const uint4*)(g_Blo + r * 256 + ch * 64 + j * 8);
            *(uint4*)(smem + OFF_BH + r * 144 + j * 16) = bh;
            *(uint4*)(smem + OFF_BL + r * 144 + j * 16) = bl;
        }
        __syncthreads();

#pragma unroll
        for (int ks = 0; ks < 4; ks++) {
            int k0 = ks * 16;
            uint32_t af[4][4], bh[4][2], bl[4][2];
#pragma unroll
            for (int mt = 0; mt < 4; mt++) {
                int r = wm * 64 + mt * 16 + g;
                const char* p = smem + OFF_AH;
                af[mt][0] = *(const uint32_t*)(p + (r * SA + k0 + t * 2) * 2);
                af[mt][1] = *(const uint32_t*)(p + ((r + 8) * SA + k0 + t * 2) * 2);
                af[mt][2] = *(const uint32_t*)(p + (r * SA + k0 + t * 2 + 8) * 2);
                af[mt][3] = *(const uint32_t*)(p + ((r + 8) * SA + k0 + t * 2 + 8) * 2);
            }
#pragma unroll
            for (int nt = 0; nt < 4; nt++) {
                int c = wn * 32 + nt * 8 + g;
                bh[nt][0] = *(const uint32_t*)(smem + OFF_BH + (c * SA + k0 + t * 2) * 2);
                bh[nt][1] = *(const uint32_t*)(smem + OFF_BH + (c * SA + k0 + t * 2 + 8) * 2);
                bl[nt][0] = *(const uint32_t*)(smem + OFF_BL + (c * SA + k0 + t * 2) * 2);
                bl[nt][1] = *(const uint32_t*)(smem + OFF_BL + (c * SA + k0 + t * 2 + 8) * 2);
            }
#pragma unroll
            for (int mt = 0; mt < 4; mt++)
#pragma unroll
                for (int nt = 0; nt < 4; nt++)
                    mma16816(acc[mt][nt][0], acc[mt][nt][1], acc[mt][nt][2], acc[mt][nt][3],
                             af[mt][0], af[mt][1], af[mt][2], af[mt][3],
                             bh[nt][0], bh[nt][1]);
#pragma unroll
            for (int mt = 0; mt < 4; mt++)
#pragma unroll
                for (int nt = 0; nt < 4; nt++)
                    mma16816(acc[mt][nt][0], acc[mt][nt][1], acc[mt][nt][2], acc[mt][nt][3],
                             af[mt][0], af[mt][1], af[mt][2], af[mt][3],
                             bl[nt][0], bl[nt][1]);
#pragma unroll
            for (int mt = 0; mt < 4; mt++) {
                int r = wm * 64 + mt * 16 + g;
                const char* p = smem + OFF_AL;
                af[mt][0] = *(const uint32_t*)(p + (r * SA + k0 + t * 2) * 2);
                af[mt][1] = *(const uint32_t*)(p + ((r + 8) * SA + k0 + t * 2) * 2);
                af[mt][2] = *(const uint32_t*)(p + (r * SA + k0 + t * 2 + 8) * 2);
                af[mt][3] = *(const uint32_t*)(p + ((r + 8) * SA + k0 + t * 2 + 8) * 2);
            }
#pragma unroll
            for (int mt = 0; mt < 4; mt++)
#pragma unroll
                for (int nt = 0; nt < 4; nt++)
                    mma16816(acc[mt][nt][0], acc[mt][nt][1], acc[mt][nt][2], acc[mt][nt][3],
                             af[mt][0], af[mt][1], af[mt][2], af[mt][3],
                             bh[nt][0], bh[nt][1]);
        }
    }
    __syncthreads();

    // epilogue: tanh(acc + bias) * fw, reduce cols -> sm_out rows
    const float* sBias = (const float*)(smem + OFF_BIAS);
    const float* sFw   = (const float*)(smem + OFF_FW);
    float* sOut        = (float*)(smem + OFF_OUT);
#pragma unroll
    for (int mt = 0; mt < 4; mt++) {
#pragma unroll
        for (int rr = 0; rr < 2; rr++) {
            int rloc = wm * 64 + mt * 16 + g + rr * 8;
            float p = 0.f;
#pragma unroll
            for (int nt = 0; nt < 4; nt++) {
#pragma unroll
                for (int cc = 0; cc < 2; cc++) {
                    int col = wn * 32 + nt * 8 + t * 2 + cc;
                    float v = acc[mt][nt][rr * 2 + cc];
                    p += tanh_ap(v + sBias[col]) * sFw[col];
                }
            }
            p += __shfl_xor_sync(0xffffffffu, p, 1);
            p += __shfl_xor_sync(0xffffffffu, p, 2);
            if (t == 0) atomicAdd(&sOut[rloc], p);
        }
    }
    __syncthreads();
    if (tid < 128) {
        int r = rowBase + tid;
        if (r < NN) y[r] = sOut[tid] + fb[0];
    }
}

// ---------------- launch -----------------------------------------------------
extern "C" void kernel_launch(void* const* d_in, const int* in_sizes, int n_in,
                              void* d_out, int out_size) {
    const float* features = (const float*)d_in[0];
    const int*   ei       = (const int*)d_in[1];
    const float* cheb_w   = (const float*)d_in[2];
    const float* cheb_b   = (const float*)d_in[3];
    const float* final_w  = (const float*)d_in[4];
    const float* final_b  = (const float*)d_in[5];
    float* y = (float*)d_out;

    static bool attr_set = false;
    if (!attr_set) {
        cudaFuncSetAttribute(k_gemm, cudaFuncAttributeMaxDynamicSharedMemorySize,
                             SMEM_DYN);
        attr_set = true;
    }

    k_fill<<<(EE + 255) / 256, 256>>>(ei);
    k_prep<<<SCALE_BLOCKS + 128, 256>>>(features, cheb_w);

    int spmm_blocks = (NN + 7) / 8;          // 8 warp-rows per 256-thread block
    k_spmm<1><<<spmm_blocks, 256>>>();
    k_spmm<2><<<spmm_blocks, 256>>>();       // profiled slot (4th launch)
    k_spmm<3><<<spmm_blocks, 256>>>();

    k_gemm<<<(NN + 127) / 128, 256, SMEM_DYN>>>(cheb_b, final_w, final_b, y);
}

// round 7
// speedup vs baseline: 1.4978x; 1.0620x over previous
#include <cuda_runtime.h>
#include <cuda_bf16.h>
#include <cstdint>

// Problem constants (fixed by the dataset)
#define NN 50000
#define EE 800000
#define FF 64
#define HH 128
#define CAP 96   // ELL capacity per row; deg ~ Poisson(16), P(deg>96) ~ 0

typedef unsigned long long ull;
typedef __nv_bfloat16 bf16;

// ---------------- scratch (static device globals; no allocations) -----------
// Scaled matrices carry ONE EXTRA ROW (index NN) that is all-zero forever:
// zero-initialized at module load and never written. ELL pad slots point at it.
__device__ int   g_cnt[NN];                 // zero-init at load; re-zeroed by k_gemm
__device__ float g_dinv[NN];
__device__ int   g_ell[(size_t)NN * CAP];   // PRE-SHIFTED: col*FF element offset
__device__ float g_XS [(size_t)(NN + 1) * FF];   // dinv * X   (+ zero row)
__device__ float g_T1S[(size_t)(NN + 1) * FF];   // dinv * T1  (+ zero row)
__device__ float g_T2S[(size_t)(NN + 1) * FF];   // dinv * T2  (+ zero row)
// bf16 hi/lo planes: GEMM inputs AND the 'prev' source for the recursion
__device__ bf16 g_Xhi [(size_t)NN * FF];
__device__ bf16 g_Xlo [(size_t)NN * FF];
__device__ bf16 g_T1hi[(size_t)NN * FF];
__device__ bf16 g_T1lo[(size_t)NN * FF];
__device__ bf16 g_T2hi[(size_t)NN * FF];
__device__ bf16 g_T2lo[(size_t)NN * FF];
__device__ bf16 g_T3hi[(size_t)NN * FF];
__device__ bf16 g_T3lo[(size_t)NN * FF];
__device__ bf16 g_Bhi[128 * 256];           // B^T hi  [h][kidx]
__device__ bf16 g_Blo[128 * 256];           // B^T lo

// ---------------- helpers ----------------------------------------------------
__device__ __forceinline__ float tanh_ap(float x) {
    float r;
    asm("tanh.approx.f32 %0, %1;" : "=f"(r) : "f"(x));
    return r;
}
__device__ __forceinline__ ull add2(ull a, ull b) {
    ull d;
    asm("add.rn.f32x2 %0, %1, %2;" : "=l"(d) : "l"(a), "l"(b));
    return d;
}
__device__ __forceinline__ void upk2(ull v, float& lo, float& hi) {
    asm("mov.b64 {%0, %1}, %2;" : "=f"(lo), "=f"(hi) : "l"(v));
}

__device__ __forceinline__ void mma16816(float& d0, float& d1, float& d2, float& d3,
                                         uint32_t a0, uint32_t a1, uint32_t a2, uint32_t a3,
                                         uint32_t b0, uint32_t b1) {
    asm volatile(
        "mma.sync.aligned.m16n8k16.row.col.f32.bf16.bf16.f32 "
        "{%0,%1,%2,%3}, {%4,%5,%6,%7}, {%8,%9}, {%0,%1,%2,%3};"
        : "+f"(d0), "+f"(d1), "+f"(d2), "+f"(d3)
        : "r"(a0), "r"(a1), "r"(a2), "r"(a3), "r"(b0), "r"(b1));
}

// split f32 pair -> packed bf16x2 hi and lo
__device__ __forceinline__ void split_hilo(float x, float y,
                                           uint32_t& hp, uint32_t& lp) {
    bf16 h0 = __float2bfloat16(x), h1 = __float2bfloat16(y);
    bf16 l0 = __float2bfloat16(x - __bfloat162float(h0));
    bf16 l1 = __float2bfloat16(y - __bfloat162float(h1));
    hp = (uint32_t)__bfloat16_as_ushort(h0) | ((uint32_t)__bfloat16_as_ushort(h1) << 16);
    lp = (uint32_t)__bfloat16_as_ushort(l0) | ((uint32_t)__bfloat16_as_ushort(l1) << 16);
}
__device__ __forceinline__ float2 bf2_to_f2(uint32_t bits) {
    __nv_bfloat162 b = *(__nv_bfloat162*)&bits;
    return __bfloat1622float2(b);
}

// ---------------- graph build ------------------------------------------------
// NOTE: g_cnt is zero on entry to every call: zero-initialized at module load,
// and re-zeroed at the head of k_gemm (which runs after all g_cnt consumers).
__global__ void k_fill(const int* __restrict__ ei) {
    int e = blockIdx.x * blockDim.x + threadIdx.x;
    if (e >= EE) return;
    int r = ei[e];
    int c = ei[EE + e];
    int s = atomicAdd(&g_cnt[r], 1);
    if (s < CAP) g_ell[(size_t)r * CAP + s] = c * FF;   // pre-shifted offset
}

// combo: blocks [0, 6250): dinv + XS = dinv*X + X hi/lo + ELL pad (warp per row)
//        blocks [6250, 6378): B^T hi/lo precompute from cheb_w
#define SCALE_BLOCKS 6250
__global__ void k_prep(const float* __restrict__ x, const float* __restrict__ W) {
    int tid = threadIdx.x;
    if (blockIdx.x < SCALE_BLOCKS) {
        int row  = blockIdx.x * 8 + (tid >> 5);
        int lane = tid & 31;
        int cnt = g_cnt[row];
        float d = (cnt > 0) ? rsqrtf((float)cnt) : 0.0f;
        if (lane == 0) g_dinv[row] = d;
        // pad ELL row to multiple of 4 with pointers to the zero row (NN)
        int c = cnt < CAP ? cnt : CAP;
        int pe = (c + 3) & ~3;
        if (lane < pe - c) g_ell[(size_t)row * CAP + c + lane] = NN * FF;
        int l2 = lane * 2;
        size_t idx = (size_t)row * FF + l2;
        float2 v = *(const float2*)(x + idx);
        uint32_t hp, lp;
        split_hilo(v.x, v.y, hp, lp);
        *(uint32_t*)(g_Xhi + idx) = hp;
        *(uint32_t*)(g_Xlo + idx) = lp;
        v.x *= d; v.y *= d;
        *(float2*)(g_XS + idx) = v;
    } else {
        int idx = (blockIdx.x - SCALE_BLOCKS) * 256 + tid;  // 0..32767
        int h = idx >> 8, kidx = idx & 255;
        int k4 = kidx >> 6, f = kidx & 63;
        float w = W[k4 * (FF * HH) + f * HH + h];
        bf16 hi = __float2bfloat16(w);
        bf16 lo = __float2bfloat16(w - __bfloat162float(hi));
        g_Bhi[h * 256 + kidx] = hi;
        g_Blo[h * 256 + kidx] = lo;
    }
}

// ---------------- SPMM: TWO rows per warp, float4 lanes ----------------------
// lanes 0-15 -> row 2w, lanes 16-31 -> row 2w+1; each lane owns 4 features.
// One LDG.128 gathers a neighbor slice for BOTH rows -> 2x rows in flight,
// half the gather instructions. ELL rows are padded to 4 with the zero row.
// prev terms reconstructed from bf16 hi/lo planes (err ~2^-17).
template <int PHASE>
__global__ __launch_bounds__(256, 6)
void k_spmm() {
    int warp = (blockIdx.x * blockDim.x + threadIdx.x) >> 5;
    int lane = threadIdx.x & 31;
    int row  = warp * 2 + (lane >> 4);
    if (row >= NN) return;
    int l4 = (lane & 15) * 4;

    const float* __restrict__ srcS = (PHASE == 1) ? g_XS
                                   : (PHASE == 2) ? g_T1S : g_T2S;
    const bf16* __restrict__ phi = (PHASE == 2) ? g_Xhi : g_T1hi;
    const bf16* __restrict__ plo = (PHASE == 2) ? g_Xlo : g_T1lo;
    bf16* __restrict__ dhi = (PHASE == 1) ? g_T1hi
                           : (PHASE == 2) ? g_T2hi : g_T3hi;
    bf16* __restrict__ dlo = (PHASE == 1) ? g_T1lo
                           : (PHASE == 2) ? g_T2lo : g_T3lo;

    float d = g_dinv[row];
    int cnt = g_cnt[row]; if (cnt > CAP) cnt = CAP;
    int cnt4 = (cnt + 3) & ~3;                 // padded bound (pad -> zero row)
    const int* ep = g_ell + (size_t)row * CAP;
    const float* srcL = srcS + l4;             // lane-adjusted base

    ull acc0 = 0ull, acc1 = 0ull;
    for (int i = 0; i < cnt4; i += 4) {
        int4 c = *(const int4*)(ep + i);
        ulonglong2 v0 = *(const ulonglong2*)(srcL + c.x);
        ulonglong2 v1 = *(const ulonglong2*)(srcL + c.y);
        ulonglong2 v2 = *(const ulonglong2*)(srcL + c.z);
        ulonglong2 v3 = *(const ulonglong2*)(srcL + c.w);
        acc0 = add2(acc0, add2(add2(v0.x, v1.x), add2(v2.x, v3.x)));
        acc1 = add2(acc1, add2(add2(v0.y, v1.y), add2(v2.y, v3.y)));
    }
    float s0, s1, s2, s3;
    upk2(acc0, s0, s1);
    upk2(acc1, s2, s3);

    size_t idx = (size_t)row * FF + l4;
    float4 res;
    if (PHASE == 1) {
        res.x = -d * s0; res.y = -d * s1; res.z = -d * s2; res.w = -d * s3;
    } else {
        uint2 hb = *(const uint2*)(phi + idx);
        uint2 lb = *(const uint2*)(plo + idx);
        float2 h01 = bf2_to_f2(hb.x), h23 = bf2_to_f2(hb.y);
        float2 l01 = bf2_to_f2(lb.x), l23 = bf2_to_f2(lb.y);
        float m = -2.f * d;
        res.x = fmaf(m, s0, -(h01.x + l01.x));
        res.y = fmaf(m, s1, -(h01.y + l01.y));
        res.z = fmaf(m, s2, -(h23.x + l23.x));
        res.w = fmaf(m, s3, -(h23.y + l23.y));
    }
    uint32_t hp0, lp0, hp1, lp1;
    split_hilo(res.x, res.y, hp0, lp0);
    split_hilo(res.z, res.w, hp1, lp1);
    *(uint2*)(dhi + idx) = make_uint2(hp0, hp1);
    *(uint2*)(dlo + idx) = make_uint2(lp0, lp1);
    if (PHASE <= 2) {
        float* dstS = (PHASE == 1) ? g_T1S : g_T2S;
        float4 rs;
        rs.x = d * res.x; rs.y = d * res.y; rs.z = d * res.z; rs.w = d * res.w;
        *(float4*)(dstS + idx) = rs;
    }
}

// ---------------- HMMA GEMM + bias + tanh + final dot ------------------------
// out[n,h] = sum_k [X|T1|T2|T3][n,:] @ W[:,h] + b[h]; y[n]=sum_h tanh(out)*fw+fb
// bf16 hi/lo split: AhiBhi + AhiBlo + AloBhi.
// CTA tile 128 rows x 128 h, K in 4 chunks of 64 (chunk == source matrix).
// Warp grid 2(m) x 4(n): warp tile 64x32 via m16n8k16 (4 m-tiles x 4 n-tiles).
// ALSO: re-zeros g_cnt for the next kernel_launch call (graph replay invariant).
#define SA 72                      // smem row stride in elements (144 B)
#define OFF_AH 0
#define OFF_AL (128 * SA * 2)      // 18432
#define OFF_BH (2 * 128 * SA * 2)
#define OFF_BL (3 * 128 * SA * 2)
#define OFF_BIAS (4 * 128 * SA * 2)        // 73728
#define OFF_FW   (OFF_BIAS + 512)
#define OFF_OUT  (OFF_FW + 512)
#define SMEM_DYN (OFF_OUT + 512)

__global__ __launch_bounds__(256)
void k_gemm(const float* __restrict__ bias, const float* __restrict__ fw,
            const float* __restrict__ fb, float* __restrict__ y) {
    extern __shared__ char smem[];
    int tid  = threadIdx.x;
    int lane = tid & 31, wid = tid >> 5;
    int wm = wid >> 2, wn = wid & 3;        // warp grid 2x4
    int g = lane >> 2, t = lane & 3;        // mma groupID / threadID-in-group
    int rowBase = blockIdx.x * 128;

    // re-zero g_cnt for next call (g_cnt consumers all ran earlier this call)
    int zi = blockIdx.x * 256 + tid;
    if (zi < NN) g_cnt[zi] = 0;

    if (tid < 128) {
        *(float*)(smem + OFF_BIAS + tid * 4) = bias[tid];
        *(float*)(smem + OFF_FW   + tid * 4) = fw[tid];
        *(float*)(smem + OFF_OUT  + tid * 4) = 0.f;
    }

    float acc[4][4][4];
#pragma unroll
    for (int a = 0; a < 4; a++)
#pragma unroll
        for (int b = 0; b < 4; b++)
#pragma unroll
            for (int c = 0; c < 4; c++) acc[a][b][c] = 0.f;

    const bf16* Ahi[4] = {g_Xhi, g_T1hi, g_T2hi, g_T3hi};
    const bf16* Alo[4] = {g_Xlo, g_T1lo, g_T2lo, g_T3lo};

    for (int ch = 0; ch < 4; ch++) {
        __syncthreads();
        const bf16* ah = Ahi[ch];
        const bf16* al = Alo[ch];
#pragma unroll
        for (int rep = 0; rep < 4; rep++) {
            int u = rep * 256 + tid;
            int r = u >> 3, j = u & 7;
            int grow = rowBase + r;
            uint4 vh = make_uint4(0, 0, 0, 0), vl = vh;
            if (grow < NN) {
                vh = *(const uint4*)(ah + (size_t)grow * FF + j * 8);
                vl = *(const uint4*)(al + (size_t)grow * FF + j * 8);
            }
            *(uint4*)(smem + OFF_AH + r * 144 + j * 16) = vh;
            *(uint4*)(smem + OFF_AL + r * 144 + j * 16) = vl;
            uint4 bh = *(const uint4*)(g_Bhi + r * 256 + ch * 64 + j * 8);
            uint4 bl = *(const uint4*)(g_Blo + r * 256 + ch * 64 + j * 8);
            *(uint4*)(smem + OFF_BH + r * 144 + j * 16) = bh;
            *(uint4*)(smem + OFF_BL + r * 144 + j * 16) = bl;
        }
        __syncthreads();

#pragma unroll
        for (int ks = 0; ks < 4; ks++) {
            int k0 = ks * 16;
            uint32_t af[4][4], bh[4][2], bl[4][2];
#pragma unroll
            for (int mt = 0; mt < 4; mt++) {
                int r = wm * 64 + mt * 16 + g;
                const char* p = smem + OFF_AH;
                af[mt][0] = *(const uint32_t*)(p + (r * SA + k0 + t * 2) * 2);
                af[mt][1] = *(const uint32_t*)(p + ((r + 8) * SA + k0 + t * 2) * 2);
                af[mt][2] = *(const uint32_t*)(p + (r * SA + k0 + t * 2 + 8) * 2);
                af[mt][3] = *(const uint32_t*)(p + ((r + 8) * SA + k0 + t * 2 + 8) * 2);
            }
#pragma unroll
            for (int nt = 0; nt < 4; nt++) {
                int c = wn * 32 + nt * 8 + g;
                bh[nt][0] = *(const uint32_t*)(smem + OFF_BH + (c * SA + k0 + t * 2) * 2);
                bh[nt][1] = *(const uint32_t*)(smem + OFF_BH + (c * SA + k0 + t * 2 + 8) * 2);
                bl[nt][0] = *(const uint32_t*)(smem + OFF_BL + (c * SA + k0 + t * 2) * 2);
                bl[nt][1] = *(const uint32_t*)(smem + OFF_BL + (c * SA + k0 + t * 2 + 8) * 2);
            }
#pragma unroll
            for (int mt = 0; mt < 4; mt++)
#pragma unroll
                for (int nt = 0; nt < 4; nt++)
                    mma16816(acc[mt][nt][0], acc[mt][nt][1], acc[mt][nt][2], acc[mt][nt][3],
                             af[mt][0], af[mt][1], af[mt][2], af[mt][3],
                             bh[nt][0], bh[nt][1]);
#pragma unroll
            for (int mt = 0; mt < 4; mt++)
#pragma unroll
                for (int nt = 0; nt < 4; nt++)
                    mma16816(acc[mt][nt][0], acc[mt][nt][1], acc[mt][nt][2], acc[mt][nt][3],
                             af[mt][0], af[mt][1], af[mt][2], af[mt][3],
                             bl[nt][0], bl[nt][1]);
#pragma unroll
            for (int mt = 0; mt < 4; mt++) {
                int r = wm * 64 + mt * 16 + g;
                const char* p = smem + OFF_AL;
                af[mt][0] = *(const uint32_t*)(p + (r * SA + k0 + t * 2) * 2);
                af[mt][1] = *(const uint32_t*)(p + ((r + 8) * SA + k0 + t * 2) * 2);
                af[mt][2] = *(const uint32_t*)(p + (r * SA + k0 + t * 2 + 8) * 2);
                af[mt][3] = *(const uint32_t*)(p + ((r + 8) * SA + k0 + t * 2 + 8) * 2);
            }
#pragma unroll
            for (int mt = 0; mt < 4; mt++)
#pragma unroll
                for (int nt = 0; nt < 4; nt++)
                    mma16816(acc[mt][nt][0], acc[mt][nt][1], acc[mt][nt][2], acc[mt][nt][3],
                             af[mt][0], af[mt][1], af[mt][2], af[mt][3],
                             bh[nt][0], bh[nt][1]);
        }
    }
    __syncthreads();

    // epilogue: tanh(acc + bias) * fw, reduce cols -> sm_out rows
    const float* sBias = (const float*)(smem + OFF_BIAS);
    const float* sFw   = (const float*)(smem + OFF_FW);
    float* sOut        = (float*)(smem + OFF_OUT);
#pragma unroll
    for (int mt = 0; mt < 4; mt++) {
#pragma unroll
        for (int rr = 0; rr < 2; rr++) {
            int rloc = wm * 64 + mt * 16 + g + rr * 8;
            float p = 0.f;
#pragma unroll
            for (int nt = 0; nt < 4; nt++) {
#pragma unroll
                for (int cc = 0; cc < 2; cc++) {
                    int col = wn * 32 + nt * 8 + t * 2 + cc;
                    float v = acc[mt][nt][rr * 2 + cc];
                    p += tanh_ap(v + sBias[col]) * sFw[col];
                }
            }
            p += __shfl_xor_sync(0xffffffffu, p, 1);
            p += __shfl_xor_sync(0xffffffffu, p, 2);
            if (t == 0) atomicAdd(&sOut[rloc], p);
        }
    }
    __syncthreads();
    if (tid < 128) {
        int r = rowBase + tid;
        if (r < NN) y[r] = sOut[tid] + fb[0];
    }
}

// ---------------- launch -----------------------------------------------------
extern "C" void kernel_launch(void* const* d_in, const int* in_sizes, int n_in,
                              void* d_out, int out_size) {
    const float* features = (const float*)d_in[0];
    const int*   ei       = (const int*)d_in[1];
    const float* cheb_w   = (const float*)d_in[2];
    const float* cheb_b   = (const float*)d_in[3];
    const float* final_w  = (const float*)d_in[4];
    const float* final_b  = (const float*)d_in[5];
    float* y = (float*)d_out;

    static bool attr_set = false;
    if (!attr_set) {
        cudaFuncSetAttribute(k_gemm, cudaFuncAttributeMaxDynamicSharedMemorySize,
                             SMEM_DYN);
        attr_set = true;
    }

    k_fill<<<(EE + 255) / 256, 256>>>(ei);
    k_prep<<<SCALE_BLOCKS + 128, 256>>>(features, cheb_w);

    int spmm_blocks = (NN / 2 + 7) / 8;      // 2 rows per warp, 8 warps per block
    k_spmm<1><<<spmm_blocks, 256>>>();
    k_spmm<2><<<spmm_blocks, 256>>>();       // profiled slot (4th launch)
    k_spmm<3><<<spmm_blocks, 256>>>();

    k_gemm<<<(NN + 127) / 128, 256, SMEM_DYN>>>(cheb_b, final_w, final_b, y);
}